// round 14
// baseline (speedup 1.0000x reference)
#include <cuda_runtime.h>
#include <cuda_fp16.h>
#include <cstdint>

// ============================================================================
// Problem constants
// ============================================================================
#define BATCH 32
#define SEQ 2048
#define MTOT (BATCH*SEQ)          // 65536
#define VOCAB 1024
#define BYTE_DIM 256
#define NUM_TABLES 32
#define BUCKETS 4096
#define HIDDEN 512

// GEMM tiling: CTA 128x128, K-chunk 64, 3-stage pipeline, 2 tiles/stage
#define TM 128
#define TN 128
#define KC 64
#define TILE_BYTES 16384          // one 128x64 fp16 tile
#define STAGE_BYTES 32768         // A, B
#define NST 3
#define MB_OFF (NST*STAGE_BYTES)  // 98304
#define GSMEM_TOTAL (MB_OFF + 64)
// mode-3 epilogue staging overlays pipeline smem: P tile 128x130 f32 + 128 tokens
#define PT_STRIDE 130
#define TOK_OFF (128*PT_STRIDE*4)   // 66560; +512 = 67072 <= 98304

// ============================================================================
// Scratch (device globals; no runtime allocation)
// Activation/weight arrays stored TILED+SWIZZLED:
//   tile id = (row>>7)*ntiles + (col>>6); within tile (r=row&127, c=col&63):
//   byte off = r*128 + ((c*2) ^ ((r&7)*16))
// ============================================================================
__device__ __align__(1024) __half g_feat[(size_t)MTOT*256];   // hash features (K=256)
__device__ __align__(1024) __half g_act[(size_t)MTOT*HIDDEN]; // ping
__device__ __align__(1024) __half g_act2[(size_t)MTOT*HIDDEN];// pong
__device__ __align__(1024) __half g_w[1310720];   // mlp(3*512*512) + w_out(1024*512), 8-tile rows
__device__ __align__(1024) __half g_w1[131072];   // w_in[:, 256:512], 4-tile rows
__device__ __align__(1024) float  g_P[VOCAB*HIDDEN]; // byte_embed @ w_in[:, :256]^T (exact f32)
__device__ int g_tok64;

// ============================================================================
// Hash constants
// ============================================================================
__constant__ unsigned long long c_primes[24] = {
    2654435761ULL, 2246822519ULL, 3266489917ULL, 2028178513ULL, 1220703125ULL,
    1610612741ULL, 805306457ULL, 402653189ULL, 3674653429ULL, 2860486313ULL,
    1073676287ULL, 2971215073ULL, 1500450271ULL, 3267000013ULL, 2654435789ULL,
    4049292737ULL, 2246822531ULL, 3266489927ULL, 2028178519ULL, 1220703133ULL,
    1610612743ULL, 805306459ULL, 402653191ULL, 3674653433ULL};
__constant__ int c_pat[NUM_TABLES][3] = {
    {1,0,0},{2,0,0},{3,0,0},{4,0,0},{5,0,0},{6,0,0},{7,0,0},{8,0,0},
    {1,2,0},{2,3,0},{3,4,0},{1,3,0},{2,4,0},{1,4,0},{1,5,0},{2,5,0},
    {3,5,0},{1,6,0},{2,6,0},{1,7,0},
    {1,2,3},{1,2,4},{1,3,5},{2,3,4},{1,2,5},{1,3,4},{2,4,6},{1,4,7},
    {1,8,0},{1,9,0},{1,10,0},{1,11,0}};
__constant__ int c_plen[NUM_TABLES] = {
    1,1,1,1,1,1,1,1, 2,2,2,2,2,2,2,2,2,2,2,2, 3,3,3,3,3,3,3,3, 2,2,2,2};

// ============================================================================
// PTX helpers (baseline sm_90-family features only)
// ============================================================================
__device__ __forceinline__ uint32_t smem_u32(const void* p) {
    uint32_t a;
    asm("{ .reg .u64 t; cvta.to.shared.u64 t, %1; cvt.u32.u64 %0, t; }" : "=r"(a) : "l"(p));
    return a;
}
__device__ __forceinline__ void mbar_init(uint32_t a, uint32_t cnt) {
    asm volatile("mbarrier.init.shared.b64 [%0], %1;" :: "r"(a), "r"(cnt) : "memory");
}
__device__ __forceinline__ void mbar_expect_tx(uint32_t a, uint32_t tx) {
    asm volatile("mbarrier.arrive.expect_tx.shared.b64 _, [%0], %1;" :: "r"(a), "r"(tx) : "memory");
}
__device__ __forceinline__ void mbar_wait(uint32_t mbar, uint32_t parity) {
    uint32_t done;
    asm volatile(
        "{\n\t.reg .pred p;\n\t"
        "mbarrier.try_wait.parity.acquire.cta.shared::cta.b64 p, [%1], %2;\n\t"
        "selp.b32 %0, 1, 0, p;\n\t}" : "=r"(done) : "r"(mbar), "r"(parity) : "memory");
    if (!done) {
        asm volatile(
            "{\n\t.reg .pred P1;\n\t"
            "WL_%=:\n\t"
            "mbarrier.try_wait.parity.acquire.cta.shared::cta.b64 P1, [%0], %1, 0x989680;\n\t"
            "@P1 bra.uni WD_%=;\n\t"
            "bra.uni WL_%=;\n\t"
            "WD_%=:\n\t}" :: "r"(mbar), "r"(parity) : "memory");
    }
}
__device__ __forceinline__ void bulk_g2s(uint32_t dst, const void* src, uint32_t bytes, uint32_t mbar) {
    asm volatile(
        "cp.async.bulk.shared::cluster.global.mbarrier::complete_tx::bytes [%0], [%1], %2, [%3];"
        :: "r"(dst), "l"(src), "r"(bytes), "r"(mbar) : "memory");
}
__device__ __forceinline__ void ldmx4(uint32_t& r0, uint32_t& r1, uint32_t& r2, uint32_t& r3, uint32_t addr) {
    asm volatile("ldmatrix.sync.aligned.m8n8.x4.shared.b16 {%0,%1,%2,%3}, [%4];"
                 : "=r"(r0), "=r"(r1), "=r"(r2), "=r"(r3) : "r"(addr));
}
__device__ __forceinline__ void mma16816(float* c, const uint32_t* a, const uint32_t* b) {
    asm volatile(
        "mma.sync.aligned.m16n8k16.row.col.f32.f16.f16.f32 "
        "{%0,%1,%2,%3}, {%4,%5,%6,%7}, {%8,%9}, {%0,%1,%2,%3};"
        : "+f"(c[0]), "+f"(c[1]), "+f"(c[2]), "+f"(c[3])
        : "r"(a[0]), "r"(a[1]), "r"(a[2]), "r"(a[3]), "r"(b[0]), "r"(b[1]));
}

// tiled-swizzled gmem byte offset; NT = tiles per 128-row block
template <int NT>
__device__ __forceinline__ size_t toff(int row, int col) {
    int r = row & 127, c = col & 63;
    return (((size_t)(row >> 7) * NT + (size_t)(col >> 6)) << 14)
         + (size_t)(r * 128 + ((c * 2) ^ ((r & 7) * 16)));
}

// ============================================================================
// Kernel 0: detect int64 vs int32 tokens (deterministic)
// ============================================================================
__global__ void init_flag_kernel() { g_tok64 = 1; }
__global__ void detect_kernel(const long long* __restrict__ c) {
    __shared__ int bad;
    if (threadIdx.x == 0) bad = 0;
    __syncthreads();
    for (int i = blockIdx.x * blockDim.x + threadIdx.x; i < MTOT / 2; i += gridDim.x * blockDim.x) {
        if ((unsigned long long)c[i] >= (unsigned long long)VOCAB) bad = 1;
    }
    __syncthreads();
    if (threadIdx.x == 0 && bad) g_tok64 = 0;  // all writers write same value
}
__device__ __forceinline__ long long get_tok(const void* chars, int idx, int is64) {
    if (is64) return ((const long long*)chars)[idx];
    return (long long)((const int*)chars)[idx];
}

// ============================================================================
// Kernel 1a: weights -> fp16 tiled. w_in cols [256,512) -> g_w1 (4-tile rows);
// mlp + w_out -> g_w (8-tile rows). w_in cols [0,256) handled exactly via g_P.
// ============================================================================
__global__ void split_w_kernel(const float* __restrict__ w_in,
                               const float* __restrict__ mlp_ws,
                               const float* __restrict__ w_out) {
    const int TOT = 262144 + 786432 + 524288;
    for (int i = blockIdx.x * blockDim.x + threadIdx.x; i < TOT; i += gridDim.x * blockDim.x) {
        if (i < 262144) {
            int R = i >> 9, k = i & 511;
            if (k >= 256)
                *(__half*)((char*)g_w1 + toff<4>(R, k - 256)) = __float2half_rn(w_in[i]);
        } else {
            int j = i - 262144;
            float v = (j < 786432) ? mlp_ws[j] : w_out[j - 786432];
            int R = j >> 9, k = j & 511;
            *(__half*)((char*)g_w + toff<8>(R, k)) = __float2half_rn(v);
        }
    }
}

// ============================================================================
// Kernel 1b: P = byte_embed @ w_in[:, :256]^T  (exact f32, 1024x512)
// ============================================================================
__global__ __launch_bounds__(256) void pproj_kernel(const float* __restrict__ byte_embed,
                                                    const float* __restrict__ w_in) {
    __shared__ float sh[4][256];
    int r0 = blockIdx.x * 4;
    int tid = threadIdx.x;
    for (int idx = tid; idx < 4 * 256; idx += 256)
        sh[idx >> 8][idx & 255] = byte_embed[(size_t)(r0 + (idx >> 8)) * BYTE_DIM + (idx & 255)];
    __syncthreads();
    float acc0[4] = {0, 0, 0, 0}, acc1[4] = {0, 0, 0, 0};
    const float* w0p = w_in + (size_t)tid * 512;
    const float* w1p = w_in + (size_t)(tid + 256) * 512;
#pragma unroll 4
    for (int k = 0; k < 256; k++) {
        float w0 = w0p[k], w1 = w1p[k];
#pragma unroll
        for (int rr = 0; rr < 4; rr++) {
            acc0[rr] += sh[rr][k] * w0;
            acc1[rr] += sh[rr][k] * w1;
        }
    }
#pragma unroll
    for (int rr = 0; rr < 4; rr++) {
        g_P[(size_t)(r0 + rr) * 512 + tid] = acc0[rr];
        g_P[(size_t)(r0 + rr) * 512 + tid + 256] = acc1[rr];
    }
}

// ============================================================================
// Kernel 2: hash features only (byte part folded into g_P) -> fp16, 4-tile rows
// one warp per token; lane = table id. LUTs staged in shared (avoid LDC replay).
// ============================================================================
__global__ __launch_bounds__(256) void embed_kernel(
    const void* __restrict__ chars,
    const float* __restrict__ hash_tables,
    __half* __restrict__ f) {
    __shared__ unsigned long long s_primes[24];
    __shared__ int s_pat[NUM_TABLES][3];
    __shared__ int s_plen[NUM_TABLES];
    {
        int tid = threadIdx.x;
        if (tid < 24) s_primes[tid] = c_primes[tid];
        if (tid < NUM_TABLES) {
            s_plen[tid] = c_plen[tid];
            s_pat[tid][0] = c_pat[tid][0];
            s_pat[tid][1] = c_pat[tid][1];
            s_pat[tid][2] = c_pat[tid][2];
        }
    }
    __syncthreads();

    int t = blockIdx.x * 8 + (threadIdx.x >> 5);
    int lane = threadIdx.x & 31;
    int s = t & (SEQ - 1);
    int is64 = g_tok64;

    int i = lane;
    int len = s_plen[i];
    long long h = 0;
#pragma unroll
    for (int k = 0; k < 3; k++) {
        if (k < len) {
            int off = s_pat[i][k];
            if (s >= off) {
                long long tok = get_tok(chars, t - off, is64);
                h ^= tok * (long long)s_primes[(i * 3 + k) % 24];
            }
        }
    }
    int idx_lo = (int)(h & 4095);
    unsigned long long sp = s_primes[(i * 3 + len) % 24];
    long long t2 = (long long)((unsigned long long)h * sp);  // wrapping mul
    long long h2 = h ^ (t2 >> 16);                           // arithmetic shift
    int idx_hi = (int)(h2 & 4095);
    float frac = (float)((int)((h >> 3) & 255)) / 255.0f * 0.4f;
    float omf = 1.0f - frac;

    const float4* tl = (const float4*)(hash_tables + ((size_t)i * BUCKETS + idx_lo) * 8);
    const float4* th = (const float4*)(hash_tables + ((size_t)i * BUCKETS + idx_hi) * 8);
    float4 l0 = tl[0], l1 = tl[1], h0 = th[0], h1 = th[1];
    float vv[8];
    vv[0] = l0.x * omf + h0.x * frac; vv[1] = l0.y * omf + h0.y * frac;
    vv[2] = l0.z * omf + h0.z * frac; vv[3] = l0.w * omf + h0.w * frac;
    vv[4] = l1.x * omf + h1.x * frac; vv[5] = l1.y * omf + h1.y * frac;
    vv[6] = l1.z * omf + h1.z * frac; vv[7] = l1.w * omf + h1.w * frac;
    __align__(16) __half hb[8];
#pragma unroll
    for (int j = 0; j < 8; j++) hb[j] = __float2half_rn(vv[j]);
    *(uint4*)((char*)f + toff<4>(t, i * 8)) = *(const uint4*)hb;
}

// ============================================================================
// Kernel 3: fp16 GEMM (C = A @ W^T), R7-style pipeline, occupancy 2.
// nchunk = K/64 (4 for layer 1, 8 otherwise); 3 stages x (A,B).
// mode 0: relu(acc+bias)                   mode 1: relu(acc+bias)+x (resid)
// mode 2: acc+bias -> f32 row-major        mode 3: relu(acc+bias+P[tok]) (layer 1)
// mode 3 stages tokens + the CTA's 128x128 P tile into smem (coalesced, L2-
// resident) after the mainloop — NOT per-thread scattered gathers (R13 lesson).
// ============================================================================
__device__ __forceinline__ void issue_chunk(uint32_t sb, int s,
                                            const char* A, const char* B, int c) {
    uint32_t mb = sb + MB_OFF + (uint32_t)s * 8;
    mbar_expect_tx(mb, STAGE_BYTES);
    uint32_t st = sb + (uint32_t)s * STAGE_BYTES;
    size_t o = (size_t)c * TILE_BYTES;
    bulk_g2s(st,              A + o, TILE_BYTES, mb);
    bulk_g2s(st + TILE_BYTES, B + o, TILE_BYTES, mb);
}

__global__ __launch_bounds__(256, 2) void gemm_kernel(
    const __half* __restrict__ a_in,
    const __half* __restrict__ w,
    const float* __restrict__ bias,
    __half* __restrict__ o_h,
    float* __restrict__ o_f,
    const void* __restrict__ chars,
    int nchunk, int mode) {
    extern __shared__ char smem[];
    uint32_t sb = smem_u32(smem);
    int tid = threadIdx.x, lane = tid & 31, wid = tid >> 5;
    int nt = blockIdx.x, mt = blockIdx.y;
    int wm = (wid >> 2) * 64, wn = (wid & 3) * 32;
    int gid = lane >> 2, t4 = lane & 3;

    const char* A = (const char*)a_in + (size_t)mt * ((size_t)nchunk * TILE_BYTES);
    const char* B = (const char*)w + (size_t)nt * ((size_t)nchunk * TILE_BYTES);

    if (tid == 0) {
#pragma unroll
        for (int s = 0; s < NST; s++) mbar_init(sb + MB_OFF + s * 8, 1);
    }
    __syncthreads();
    if (tid == 0) {
        issue_chunk(sb, 0, A, B, 0);
        issue_chunk(sb, 1, A, B, 1);
    }

    float acc[4][4][4];
#pragma unroll
    for (int i = 0; i < 4; i++)
#pragma unroll
        for (int j = 0; j < 4; j++)
#pragma unroll
            for (int k = 0; k < 4; k++) acc[i][j][k] = 0.0f;

    // ldmatrix per-thread address components
    int la = lane & 7;
    int aq8  = ((lane >> 3) & 1) * 8;    // A: quad&1 -> +8 rows
    int ak16 = ((lane >> 4) & 1) * 16;   // A: quad>>1 -> +16 k-bytes
    int bq8  = ((lane >> 4) & 1) * 8;    // B: quad>>1 -> +8 rows
    int bk16 = ((lane >> 3) & 1) * 16;   // B: quad&1 -> +16 k-bytes

    for (int c = 0; c < nchunk; c++) {
        int s = c % NST;
        mbar_wait(sb + MB_OFF + (uint32_t)s * 8, (uint32_t)((c / NST) & 1));
        __syncthreads();   // all warps past previous use of the stage to be overwritten
        if (c + 2 < nchunk && tid == 0)
            issue_chunk(sb, (c + 2) % NST, A, B, c + 2);

        uint32_t st = sb + (uint32_t)s * STAGE_BYTES;
        uint32_t stB = st + TILE_BYTES;

#pragma unroll
        for (int k16 = 0; k16 < 4; k16++) {
            int kb = k16 * 32;
            uint32_t bh[4][2];
#pragma unroll
            for (int jp = 0; jp < 2; jp++) {
                int rowb = wn + jp * 16 + la + bq8;
                uint32_t off = (uint32_t)(rowb * 128 + ((kb + bk16) ^ ((rowb & 7) * 16)));
                ldmx4(bh[jp*2][0], bh[jp*2][1], bh[jp*2+1][0], bh[jp*2+1][1], stB + off);
            }
#pragma unroll
            for (int i = 0; i < 4; i++) {
                int rowa = wm + i * 16 + la + aq8;
                uint32_t off = (uint32_t)(rowa * 128 + ((kb + ak16) ^ ((rowa & 7) * 16)));
                uint32_t ah[4];
                ldmx4(ah[0], ah[1], ah[2], ah[3], st + off);
#pragma unroll
                for (int j = 0; j < 4; j++) mma16816(acc[i][j], ah, bh[j]);
            }
        }
    }

    int ntbase = nt * 128;

    // ---- mode-3 staging: tokens + coalesced 128x128 P tile into (free) smem
    float* Pt = (float*)smem;
    if (mode == 3) {
        __syncthreads();   // all warps done with pipeline smem
        int* tokv = (int*)(smem + TOK_OFF);
        if (tid < 128) tokv[tid] = (int)get_tok(chars, mt * 128 + tid, g_tok64);
        __syncthreads();
#pragma unroll 4
        for (int i = tid; i < 128 * 128; i += 256) {
            int r = i >> 7, cc = i & 127;
            Pt[r * PT_STRIDE + cc] = g_P[(size_t)tokv[r] * 512 + ntbase + cc];
        }
        __syncthreads();
    }

    // ---- epilogue: regs -> gmem directly
#pragma unroll
    for (int i = 0; i < 4; i++) {
#pragma unroll
        for (int j = 0; j < 4; j++) {
#pragma unroll
            for (int p = 0; p < 2; p++) {
                int rloc = wm + i * 16 + p * 8 + gid;      // 0..127
                int cloc = wn + j * 8 + t4 * 2;            // 0..127
                float2 bb = *(const float2*)(bias + ntbase + cloc);
                float v0 = acc[i][j][p * 2] + bb.x;
                float v1 = acc[i][j][p * 2 + 1] + bb.y;
                if (mode == 2) {
                    int m = mt * 128 + rloc;
                    float2 r; r.x = v0; r.y = v1;
                    *(float2*)(o_f + (size_t)m * 1024 + ntbase + cloc) = r;
                } else {
                    if (mode == 3) {
                        float2 pv = *(const float2*)(Pt + rloc * PT_STRIDE + cloc);
                        v0 += pv.x; v1 += pv.y;
                    }
                    v0 = fmaxf(v0, 0.0f);
                    v1 = fmaxf(v1, 0.0f);
                    size_t off = (((size_t)(mt * 8 + nt * 2 + (cloc >> 6))) << 14)
                               + (size_t)(rloc * 128 + (((cloc & 63) * 2) ^ ((rloc & 7) * 16)));
                    if (mode == 1) {
                        __half2 xh = *(const __half2*)((const char*)a_in + off);
                        v0 += __half2float(xh.x);
                        v1 += __half2float(xh.y);
                    }
                    __half2 ho; ho.x = __float2half_rn(v0); ho.y = __float2half_rn(v1);
                    *(__half2*)((char*)o_h + off) = ho;
                }
            }
        }
    }
}

// ============================================================================
// Host launch
// ============================================================================
extern "C" void kernel_launch(void* const* d_in, const int* in_sizes, int n_in,
                              void* d_out, int out_size) {
    (void)in_sizes; (void)n_in; (void)out_size;
    const void* chars = d_in[0];
    const float* byte_embed = (const float*)d_in[1];
    const float* hash_tables = (const float*)d_in[2];
    const float* w_in = (const float*)d_in[3];
    const float* b_in = (const float*)d_in[4];
    const float* mlp_ws = (const float*)d_in[5];
    const float* mlp_bs = (const float*)d_in[6];
    const float* w_out = (const float*)d_in[7];
    const float* b_out = (const float*)d_in[8];
    float* out = (float*)d_out;

    cudaFuncSetAttribute(gemm_kernel, cudaFuncAttributeMaxDynamicSharedMemorySize, GSMEM_TOTAL);

    void *p_f, *p_a, *p_a2, *p_w, *p_w1;
    cudaGetSymbolAddress(&p_f, g_feat);
    cudaGetSymbolAddress(&p_a, g_act);
    cudaGetSymbolAddress(&p_a2, g_act2);
    cudaGetSymbolAddress(&p_w, g_w);
    cudaGetSymbolAddress(&p_w1, g_w1);
    __half* f = (__half*)p_f;
    __half* a = (__half*)p_a;
    __half* a2 = (__half*)p_a2;
    __half* w = (__half*)p_w;
    __half* w1 = (__half*)p_w1;

    init_flag_kernel<<<1, 1>>>();
    detect_kernel<<<64, 256>>>((const long long*)chars);
    pproj_kernel<<<256, 256>>>(byte_embed, w_in);
    split_w_kernel<<<768, 512>>>(w_in, mlp_ws, w_out);
    embed_kernel<<<MTOT / 8, 256>>>(chars, hash_tables, f);

    dim3 gh(4, 512), gf(8, 512);
    // layer 1 (K=256 hash part; byte part via staged g_P tile): feat -> act
    gemm_kernel<<<gh, 256, GSMEM_TOTAL>>>(f, w1, b_in, a, nullptr, chars, 4, 3);
    // residual blocks (ping-pong act<->act2), K=512
    gemm_kernel<<<gh, 256, GSMEM_TOTAL>>>(a, w, mlp_bs, a2, nullptr, nullptr, 8, 1);
    gemm_kernel<<<gh, 256, GSMEM_TOTAL>>>(a2, w + 262144, mlp_bs + 512, a, nullptr, nullptr, 8, 1);
    gemm_kernel<<<gh, 256, GSMEM_TOTAL>>>(a, w + 524288, mlp_bs + 1024, a2, nullptr, nullptr, 8, 1);
    // output layer: act2 -> logits (f32, ld 1024), K=512
    gemm_kernel<<<gf, 256, GSMEM_TOTAL>>>(a2, w + 786432, b_out, nullptr, out, nullptr, 8, 2);
}

// round 15
// speedup vs baseline: 1.3379x; 1.3379x over previous
#include <cuda_runtime.h>
#include <cuda_fp16.h>
#include <cstdint>

// ============================================================================
// Problem constants
// ============================================================================
#define BATCH 32
#define SEQ 2048
#define MTOT (BATCH*SEQ)          // 65536
#define VOCAB 1024
#define BYTE_DIM 256
#define NUM_TABLES 32
#define BUCKETS 4096
#define HIDDEN 512
#define WTOT 1572864              // 4*512*512 + 1024*512

// GEMM tiling: CTA 128x128, K-chunk 64, 3-stage pipeline, 2 tiles/stage
#define TM 128
#define TN 128
#define KC 64
#define NCHUNK (HIDDEN/KC)        // 8
#define TILE_BYTES 16384          // one 128x64 fp16 tile
#define STAGE_BYTES 32768         // A, B
#define NST 3
#define MB_OFF (NST*STAGE_BYTES)  // 98304
#define GSMEM_TOTAL (MB_OFF + 64)

// ============================================================================
// Scratch (device globals; no runtime allocation)
// All activation/weight arrays are stored TILED+SWIZZLED:
//   tile id = (row>>7)*8 + (col>>6); within tile (r=row&127, c=col&63):
//   byte off = r*128 + ((c*2) ^ ((r&7)*16))
// ============================================================================
__device__ __align__(1024) __half g_feat[(size_t)MTOT*HIDDEN];
__device__ __align__(1024) __half g_act[(size_t)MTOT*HIDDEN];
__device__ __align__(1024) __half g_w[WTOT];
__device__ int g_tok64;

// ============================================================================
// Hash constants
// ============================================================================
__constant__ unsigned long long c_primes[24] = {
    2654435761ULL, 2246822519ULL, 3266489917ULL, 2028178513ULL, 1220703125ULL,
    1610612741ULL, 805306457ULL, 402653189ULL, 3674653429ULL, 2860486313ULL,
    1073676287ULL, 2971215073ULL, 1500450271ULL, 3267000013ULL, 2654435789ULL,
    4049292737ULL, 2246822531ULL, 3266489927ULL, 2028178519ULL, 1220703133ULL,
    1610612743ULL, 805306459ULL, 402653191ULL, 3674653433ULL};
__constant__ int c_pat[NUM_TABLES][3] = {
    {1,0,0},{2,0,0},{3,0,0},{4,0,0},{5,0,0},{6,0,0},{7,0,0},{8,0,0},
    {1,2,0},{2,3,0},{3,4,0},{1,3,0},{2,4,0},{1,4,0},{1,5,0},{2,5,0},
    {3,5,0},{1,6,0},{2,6,0},{1,7,0},
    {1,2,3},{1,2,4},{1,3,5},{2,3,4},{1,2,5},{1,3,4},{2,4,6},{1,4,7},
    {1,8,0},{1,9,0},{1,10,0},{1,11,0}};
__constant__ int c_plen[NUM_TABLES] = {
    1,1,1,1,1,1,1,1, 2,2,2,2,2,2,2,2,2,2,2,2, 3,3,3,3,3,3,3,3, 2,2,2,2};

// ============================================================================
// PTX helpers (baseline sm_90-family features only)
// ============================================================================
__device__ __forceinline__ uint32_t smem_u32(const void* p) {
    uint32_t a;
    asm("{ .reg .u64 t; cvta.to.shared.u64 t, %1; cvt.u32.u64 %0, t; }" : "=r"(a) : "l"(p));
    return a;
}
__device__ __forceinline__ void mbar_init(uint32_t a, uint32_t cnt) {
    asm volatile("mbarrier.init.shared.b64 [%0], %1;" :: "r"(a), "r"(cnt) : "memory");
}
__device__ __forceinline__ void mbar_expect_tx(uint32_t a, uint32_t tx) {
    asm volatile("mbarrier.arrive.expect_tx.shared.b64 _, [%0], %1;" :: "r"(a), "r"(tx) : "memory");
}
__device__ __forceinline__ void mbar_wait(uint32_t mbar, uint32_t parity) {
    uint32_t done;
    asm volatile(
        "{\n\t.reg .pred p;\n\t"
        "mbarrier.try_wait.parity.acquire.cta.shared::cta.b64 p, [%1], %2;\n\t"
        "selp.b32 %0, 1, 0, p;\n\t}" : "=r"(done) : "r"(mbar), "r"(parity) : "memory");
    if (!done) {
        asm volatile(
            "{\n\t.reg .pred P1;\n\t"
            "WL_%=:\n\t"
            "mbarrier.try_wait.parity.acquire.cta.shared::cta.b64 P1, [%0], %1, 0x989680;\n\t"
            "@P1 bra.uni WD_%=;\n\t"
            "bra.uni WL_%=;\n\t"
            "WD_%=:\n\t}" :: "r"(mbar), "r"(parity) : "memory");
    }
}
__device__ __forceinline__ void bulk_g2s(uint32_t dst, const void* src, uint32_t bytes, uint32_t mbar) {
    asm volatile(
        "cp.async.bulk.shared::cluster.global.mbarrier::complete_tx::bytes [%0], [%1], %2, [%3];"
        :: "r"(dst), "l"(src), "r"(bytes), "r"(mbar) : "memory");
}
__device__ __forceinline__ void ldmx4(uint32_t& r0, uint32_t& r1, uint32_t& r2, uint32_t& r3, uint32_t addr) {
    asm volatile("ldmatrix.sync.aligned.m8n8.x4.shared.b16 {%0,%1,%2,%3}, [%4];"
                 : "=r"(r0), "=r"(r1), "=r"(r2), "=r"(r3) : "r"(addr));
}
__device__ __forceinline__ void mma16816(float* c, const uint32_t* a, const uint32_t* b) {
    asm volatile(
        "mma.sync.aligned.m16n8k16.row.col.f32.f16.f16.f32 "
        "{%0,%1,%2,%3}, {%4,%5,%6,%7}, {%8,%9}, {%0,%1,%2,%3};"
        : "+f"(c[0]), "+f"(c[1]), "+f"(c[2]), "+f"(c[3])
        : "r"(a[0]), "r"(a[1]), "r"(a[2]), "r"(a[3]), "r"(b[0]), "r"(b[1]));
}

// tiled-swizzled gmem byte offset for [.,512] fp16 arrays
__device__ __forceinline__ size_t toff(int row, int col) {
    int r = row & 127, c = col & 63;
    return (((size_t)(row >> 7) * 8 + (size_t)(col >> 6)) << 14)
         + (size_t)(r * 128 + ((c * 2) ^ ((r & 7) * 16)));
}

// ============================================================================
// Kernel 0: detect int64 vs int32 tokens (deterministic)
// ============================================================================
__global__ void init_flag_kernel() { g_tok64 = 1; }
__global__ void detect_kernel(const long long* __restrict__ c) {
    __shared__ int bad;
    if (threadIdx.x == 0) bad = 0;
    __syncthreads();
    for (int i = blockIdx.x * blockDim.x + threadIdx.x; i < MTOT / 2; i += gridDim.x * blockDim.x) {
        if ((unsigned long long)c[i] >= (unsigned long long)VOCAB) bad = 1;
    }
    __syncthreads();
    if (threadIdx.x == 0 && bad) g_tok64 = 0;  // all writers write same value
}
__device__ __forceinline__ long long get_tok(const void* chars, int idx, int is64) {
    if (is64) return ((const long long*)chars)[idx];
    return (long long)((const int*)chars)[idx];
}

// ============================================================================
// Kernel 1: round weights to fp16 in tiled-swizzled layout
// ============================================================================
__global__ void split_w_kernel(const float* __restrict__ w_in,
                               const float* __restrict__ mlp_ws,
                               const float* __restrict__ w_out) {
    for (int i = blockIdx.x * blockDim.x + threadIdx.x; i < WTOT; i += gridDim.x * blockDim.x) {
        float v;
        if (i < 262144) v = w_in[i];
        else if (i < 1048576) v = mlp_ws[i - 262144];
        else v = w_out[i - 1048576];
        int R = i >> 9, k = i & 511;
        *(__half*)((char*)g_w + toff(R, k)) = __float2half_rn(v);
    }
}

// ============================================================================
// Kernel 2: features (byte embed + 32 soft-hash tables) -> fp16 tiled
// one warp per token; lane = table id. LUTs staged in shared (avoid LDC replay).
// ============================================================================
__device__ __forceinline__ void store8(char* p, const float* v) {
    __align__(16) __half hb[8];
#pragma unroll
    for (int j = 0; j < 8; j++) hb[j] = __float2half_rn(v[j]);
    *(uint4*)p = *(const uint4*)hb;
}

__global__ __launch_bounds__(256) void embed_kernel(
    const void* __restrict__ chars,
    const float* __restrict__ byte_embed,
    const float* __restrict__ hash_tables,
    __half* __restrict__ f) {
    __shared__ unsigned long long s_primes[24];
    __shared__ int s_pat[NUM_TABLES][3];
    __shared__ int s_plen[NUM_TABLES];
    {
        int tid = threadIdx.x;
        if (tid < 24) s_primes[tid] = c_primes[tid];
        if (tid < NUM_TABLES) {
            s_plen[tid] = c_plen[tid];
            s_pat[tid][0] = c_pat[tid][0];
            s_pat[tid][1] = c_pat[tid][1];
            s_pat[tid][2] = c_pat[tid][2];
        }
    }
    __syncthreads();

    int t = blockIdx.x * 8 + (threadIdx.x >> 5);
    int lane = threadIdx.x & 31;
    int s = t & (SEQ - 1);
    int is64 = g_tok64;

    // byte embedding: 256 floats, 8 per lane -> cols lane*8
    {
        long long tok0 = get_tok(chars, t, is64);
        const float4* row = (const float4*)(byte_embed + (size_t)tok0 * BYTE_DIM);
        float4 v0 = row[lane * 2], v1 = row[lane * 2 + 1];
        float vv[8] = {v0.x, v0.y, v0.z, v0.w, v1.x, v1.y, v1.z, v1.w};
        store8((char*)f + toff(t, lane * 8), vv);
    }

    // hash tables: lane i handles table i -> cols 256 + i*8
    int i = lane;
    int len = s_plen[i];
    long long h = 0;
#pragma unroll
    for (int k = 0; k < 3; k++) {
        if (k < len) {
            int off = s_pat[i][k];
            if (s >= off) {
                long long tok = get_tok(chars, t - off, is64);
                h ^= tok * (long long)s_primes[(i * 3 + k) % 24];
            }
        }
    }
    int idx_lo = (int)(h & 4095);
    unsigned long long sp = s_primes[(i * 3 + len) % 24];
    long long t2 = (long long)((unsigned long long)h * sp);  // wrapping mul
    long long h2 = h ^ (t2 >> 16);                           // arithmetic shift
    int idx_hi = (int)(h2 & 4095);
    float frac = (float)((int)((h >> 3) & 255)) / 255.0f * 0.4f;
    float omf = 1.0f - frac;

    const float4* tl = (const float4*)(hash_tables + ((size_t)i * BUCKETS + idx_lo) * 8);
    const float4* th = (const float4*)(hash_tables + ((size_t)i * BUCKETS + idx_hi) * 8);
    float4 l0 = tl[0], l1 = tl[1], h0 = th[0], h1 = th[1];
    float vv[8];
    vv[0] = l0.x * omf + h0.x * frac; vv[1] = l0.y * omf + h0.y * frac;
    vv[2] = l0.z * omf + h0.z * frac; vv[3] = l0.w * omf + h0.w * frac;
    vv[4] = l1.x * omf + h1.x * frac; vv[5] = l1.y * omf + h1.y * frac;
    vv[6] = l1.z * omf + h1.z * frac; vv[7] = l1.w * omf + h1.w * frac;
    store8((char*)f + toff(t, BYTE_DIM + i * 8), vv);
}

// ============================================================================
// Kernel 3: fp16 GEMM (C = A @ W^T), R7-style pipeline, occupancy 2.
// Compile-time MODE (no runtime branches in the hot kernel):
//   MODE 0: relu(acc+bias)            MODE 1: relu(acc+bias)+x (resid)
//   MODE 2: acc+bias -> f32 row-major (ld 1024)
// ============================================================================
__device__ __forceinline__ void issue_chunk(uint32_t sb, int s,
                                            const char* A, const char* B, int c) {
    uint32_t mb = sb + MB_OFF + (uint32_t)s * 8;
    mbar_expect_tx(mb, STAGE_BYTES);
    uint32_t st = sb + (uint32_t)s * STAGE_BYTES;
    size_t o = (size_t)c * TILE_BYTES;
    bulk_g2s(st,              A + o, TILE_BYTES, mb);
    bulk_g2s(st + TILE_BYTES, B + o, TILE_BYTES, mb);
}

template <int MODE>
__global__ __launch_bounds__(256, 2) void gemm_kernel(
    const __half* __restrict__ a_in,
    const __half* __restrict__ w,
    const float* __restrict__ bias,
    __half* __restrict__ o_h,
    float* __restrict__ o_f) {
    extern __shared__ char smem[];
    uint32_t sb = smem_u32(smem);
    int tid = threadIdx.x, lane = tid & 31, wid = tid >> 5;
    int nt = blockIdx.x, mt = blockIdx.y;
    int wm = (wid >> 2) * 64, wn = (wid & 3) * 32;
    int gid = lane >> 2, t4 = lane & 3;

    const char* A = (const char*)a_in + (size_t)mt * (8 * TILE_BYTES);
    const char* B = (const char*)w + (size_t)nt * (8 * TILE_BYTES);

    if (tid == 0) {
#pragma unroll
        for (int s = 0; s < NST; s++) mbar_init(sb + MB_OFF + s * 8, 1);
    }
    __syncthreads();
    if (tid == 0) {
        issue_chunk(sb, 0, A, B, 0);
        issue_chunk(sb, 1, A, B, 1);
    }

    float acc[4][4][4];
#pragma unroll
    for (int i = 0; i < 4; i++)
#pragma unroll
        for (int j = 0; j < 4; j++)
#pragma unroll
            for (int k = 0; k < 4; k++) acc[i][j][k] = 0.0f;

    // ldmatrix per-thread address components
    int la = lane & 7;
    int aq8  = ((lane >> 3) & 1) * 8;    // A: quad&1 -> +8 rows
    int ak16 = ((lane >> 4) & 1) * 16;   // A: quad>>1 -> +16 k-bytes
    int bq8  = ((lane >> 4) & 1) * 8;    // B: quad>>1 -> +8 rows
    int bk16 = ((lane >> 3) & 1) * 16;   // B: quad&1 -> +16 k-bytes

    for (int c = 0; c < NCHUNK; c++) {
        int s = c % NST;
        mbar_wait(sb + MB_OFF + (uint32_t)s * 8, (uint32_t)((c / NST) & 1));
        __syncthreads();   // all warps past previous use of the stage to be overwritten
        if (c + 2 < NCHUNK && tid == 0)
            issue_chunk(sb, (c + 2) % NST, A, B, c + 2);

        uint32_t st = sb + (uint32_t)s * STAGE_BYTES;
        uint32_t stB = st + TILE_BYTES;

#pragma unroll
        for (int k16 = 0; k16 < 4; k16++) {
            int kb = k16 * 32;
            uint32_t bh[4][2];
#pragma unroll
            for (int jp = 0; jp < 2; jp++) {
                int rowb = wn + jp * 16 + la + bq8;
                uint32_t off = (uint32_t)(rowb * 128 + ((kb + bk16) ^ ((rowb & 7) * 16)));
                ldmx4(bh[jp*2][0], bh[jp*2][1], bh[jp*2+1][0], bh[jp*2+1][1], stB + off);
            }
#pragma unroll
            for (int i = 0; i < 4; i++) {
                int rowa = wm + i * 16 + la + aq8;
                uint32_t off = (uint32_t)(rowa * 128 + ((kb + ak16) ^ ((rowa & 7) * 16)));
                uint32_t ah[4];
                ldmx4(ah[0], ah[1], ah[2], ah[3], st + off);
#pragma unroll
                for (int j = 0; j < 4; j++) mma16816(acc[i][j], ah, bh[j]);
            }
        }
    }

    // ---- epilogue: regs -> gmem directly
    int ntbase = nt * 128;
#pragma unroll
    for (int i = 0; i < 4; i++) {
#pragma unroll
        for (int j = 0; j < 4; j++) {
#pragma unroll
            for (int p = 0; p < 2; p++) {
                int rloc = wm + i * 16 + p * 8 + gid;      // 0..127
                int cloc = wn + j * 8 + t4 * 2;            // 0..127
                float2 bb = *(const float2*)(bias + ntbase + cloc);
                float v0 = acc[i][j][p * 2] + bb.x;
                float v1 = acc[i][j][p * 2 + 1] + bb.y;
                if (MODE == 2) {
                    int m = mt * 128 + rloc;
                    float2 r; r.x = v0; r.y = v1;
                    *(float2*)(o_f + (size_t)m * 1024 + ntbase + cloc) = r;
                } else {
                    v0 = fmaxf(v0, 0.0f);
                    v1 = fmaxf(v1, 0.0f);
                    size_t off = (((size_t)(mt * 8 + nt * 2 + (cloc >> 6))) << 14)
                               + (size_t)(rloc * 128 + (((cloc & 63) * 2) ^ ((rloc & 7) * 16)));
                    if (MODE == 1) {
                        __half2 xh = *(const __half2*)((const char*)a_in + off);
                        v0 += __half2float(xh.x);
                        v1 += __half2float(xh.y);
                    }
                    __half2 ho; ho.x = __float2half_rn(v0); ho.y = __float2half_rn(v1);
                    *(__half2*)((char*)o_h + off) = ho;
                }
            }
        }
    }
}

// ============================================================================
// Host launch
// ============================================================================
extern "C" void kernel_launch(void* const* d_in, const int* in_sizes, int n_in,
                              void* d_out, int out_size) {
    (void)in_sizes; (void)n_in; (void)out_size;
    const void* chars = d_in[0];
    const float* byte_embed = (const float*)d_in[1];
    const float* hash_tables = (const float*)d_in[2];
    const float* w_in = (const float*)d_in[3];
    const float* b_in = (const float*)d_in[4];
    const float* mlp_ws = (const float*)d_in[5];
    const float* mlp_bs = (const float*)d_in[6];
    const float* w_out = (const float*)d_in[7];
    const float* b_out = (const float*)d_in[8];
    float* out = (float*)d_out;

    cudaFuncSetAttribute(gemm_kernel<0>, cudaFuncAttributeMaxDynamicSharedMemorySize, GSMEM_TOTAL);
    cudaFuncSetAttribute(gemm_kernel<1>, cudaFuncAttributeMaxDynamicSharedMemorySize, GSMEM_TOTAL);
    cudaFuncSetAttribute(gemm_kernel<2>, cudaFuncAttributeMaxDynamicSharedMemorySize, GSMEM_TOTAL);

    void *p_f, *p_a, *p_w;
    cudaGetSymbolAddress(&p_f, g_feat);
    cudaGetSymbolAddress(&p_a, g_act);
    cudaGetSymbolAddress(&p_w, g_w);
    __half* f = (__half*)p_f;
    __half* a = (__half*)p_a;
    __half* w = (__half*)p_w;

    init_flag_kernel<<<1, 1>>>();
    detect_kernel<<<64, 256>>>((const long long*)chars);
    split_w_kernel<<<768, 512>>>(w_in, mlp_ws, w_out);
    embed_kernel<<<MTOT / 8, 256>>>(chars, byte_embed, hash_tables, f);

    dim3 gh(4, 512), gf(8, 512);
    // layer 1: feat -> act
    gemm_kernel<0><<<gh, 256, GSMEM_TOTAL>>>(f, w, b_in, a, nullptr);
    // residual blocks (ping-pong feat<->act)
    gemm_kernel<1><<<gh, 256, GSMEM_TOTAL>>>(a, w + 262144, mlp_bs, f, nullptr);
    gemm_kernel<1><<<gh, 256, GSMEM_TOTAL>>>(f, w + 524288, mlp_bs + 512, a, nullptr);
    gemm_kernel<1><<<gh, 256, GSMEM_TOTAL>>>(a, w + 786432, mlp_bs + 1024, f, nullptr);
    // output layer: feat -> logits (f32, ld 1024)
    gemm_kernel<2><<<gf, 256, GSMEM_TOTAL>>>(f, w + 1048576, b_out, nullptr, out);
}